// round 10
// baseline (speedup 1.0000x reference)
#include <cuda_runtime.h>
#include <cstdint>

// Problem constants
#define Bc   4
#define Cc   256
#define Hc   64
#define Wc   64
#define OCc  256
#define Kc   9
#define Pc   4096
#define CKc  (Cc*Kc)    // 2304

// tf32-rounded, K-reordered weights: g_wtf[oc][k*256 + c]
__device__ float g_wtf[(size_t)OCc * CKc];

__device__ __forceinline__ uint32_t cvt_tf32(float f) {
    uint32_t r;
    asm("cvt.rna.tf32.f32 %0, %1;" : "=r"(r) : "f"(f));
    return r;
}

// ---------------------------------------------------------------------------
// Stage 0: round weights to tf32 AND reorder K: [oc][c*9+k] -> [oc][k*256+c]
// ---------------------------------------------------------------------------
__global__ __launch_bounds__(256) void round_weights(const float* __restrict__ w) {
    int i = blockIdx.x * 256 + threadIdx.x;
    if (i < OCc * CKc) {
        int oc = i / CKc;
        int rr = i - oc * CKc;       // rr = k*256 + c
        int k  = rr >> 8;
        int c  = rr & 255;
        g_wtf[i] = __uint_as_float(cvt_tf32(w[(size_t)oc * CKc + c * 9 + k]));
    }
}

// ---------------------------------------------------------------------------
// Fused kernel: 8 mma warps (tf32 mma.sync GEMM, BM=128 BN=128 BK=32) +
// 2 producer warps that build each B tile (1 tap x 32 channels x 128 p)
// in shared memory from x/offset (deformable bilinear gather).
// ---------------------------------------------------------------------------
#define BM 128
#define BN 128
#define BK 32
#define NT (CKc / BK)      // 72 = 9 taps x 8 channel-tiles
#define ASTAGES 3
#define ASTRB 144          // A smem row stride BYTES (ldmatrix conflict-free)
#define ABYTES (BM * ASTRB)            // 18432
#define BSTR 136           // B smem row stride (words) - LDS conflict-free
#define BBYTES (BK * BSTR * 4)         // 17408
#define META_N (Kc * BN)               // 1152
#define OFF_B   (ASTAGES * ABYTES)               // 55296
#define OFF_MW  (OFF_B + 2 * BBYTES)             // 90112
#define OFF_MI  (OFF_MW + META_N * 16)           // 108544
#define SM_TOTAL (OFF_MI + META_N * 4)           // 113152

#define NTHREADS 320      // 256 consumer + 64 producer
#define NCONS    256

__device__ __forceinline__ uint32_t smem_u32(const void* p) {
    uint32_t a;
    asm("{ .reg .u64 t; cvta.to.shared.u64 t, %1; cvt.u32.u64 %0, t; }"
        : "=r"(a) : "l"(p));
    return a;
}
__device__ __forceinline__ void cp_async16(uint32_t dst, const void* src) {
    asm volatile("cp.async.cg.shared.global [%0], [%1], 16;"
                 :: "r"(dst), "l"(src) : "memory");
}
__device__ __forceinline__ void cp_commit() {
    asm volatile("cp.async.commit_group;" ::: "memory");
}
template <int N>
__device__ __forceinline__ void cp_wait() {
    asm volatile("cp.async.wait_group %0;" :: "n"(N) : "memory");
}
__device__ __forceinline__ void ldmx4(uint32_t addr, uint32_t r[4]) {
    asm volatile("ldmatrix.sync.aligned.m8n8.x4.shared.b16 {%0,%1,%2,%3}, [%4];"
                 : "=r"(r[0]), "=r"(r[1]), "=r"(r[2]), "=r"(r[3]) : "r"(addr));
}
__device__ __forceinline__ void mma_tf32(float c[4],
                                         uint32_t a0, uint32_t a1, uint32_t a2, uint32_t a3,
                                         uint32_t b0, uint32_t b1) {
    asm volatile(
        "mma.sync.aligned.m16n8k8.row.col.f32.tf32.tf32.f32 "
        "{%0,%1,%2,%3}, {%4,%5,%6,%7}, {%8,%9}, {%0,%1,%2,%3};"
        : "+f"(c[0]), "+f"(c[1]), "+f"(c[2]), "+f"(c[3])
        : "r"(a0), "r"(a1), "r"(a2), "r"(a3), "r"(b0), "r"(b1));
}

__global__ __launch_bounds__(NTHREADS, 2) void dcn_fused(
    const float* __restrict__ x,        // [B,C,H,W]
    const float* __restrict__ offset,   // [B,18,H,W]
    float* __restrict__ out)            // [B,OC,P]
{
    extern __shared__ char smraw[];
    const uint32_t sbA = smem_u32(smraw);
    float*    Bs    = (float*)(smraw + OFF_B);
    float4*   metaW = (float4*)(smraw + OFF_MW);
    uint32_t* metaI = (uint32_t*)(smraw + OFF_MI);

    const int tid = threadIdx.x;
    const int bx = blockIdx.x;         // N tile (0..31)
    const int by = blockIdx.y;         // M tile (0..1)
    const int b  = blockIdx.z;         // batch
    const int p0 = bx * BN;

    // ---- metadata: 1152 (tap, p) entries, all threads ----
    for (int e = tid; e < META_N; e += NTHREADS) {
        int k = e >> 7;
        int pl = e & 127;
        int pg = p0 + pl;
        int ho = pg >> 6, wo = pg & 63;
        int ki = k / 3, kj = k - 3 * ki;

        const float* offb = offset + ((size_t)b * 18) * Pc;
        float dy = offb[(2 * k    ) * Pc + pg];
        float dx = offb[(2 * k + 1) * Pc + pg];

        float ph = (float)(ho - 1 + ki) + dy;
        float pw = (float)(wo - 1 + kj) + dx;
        float h0f = floorf(ph), w0f = floorf(pw);
        float lh = ph - h0f,    lw = pw - w0f;
        int h0 = (int)h0f, w0 = (int)w0f;
        int h1 = h0 + 1,   w1 = w0 + 1;

        float vh0 = (h0 >= 0 && h0 < Hc) ? 1.f : 0.f;
        float vh1 = (h1 >= 0 && h1 < Hc) ? 1.f : 0.f;
        float vw0 = (w0 >= 0 && w0 < Wc) ? 1.f : 0.f;
        float vw1 = (w1 >= 0 && w1 < Wc) ? 1.f : 0.f;

        float4 wv;
        wv.x = (1.f - lh) * (1.f - lw) * vh0 * vw0;
        wv.y = (1.f - lh) * lw         * vh0 * vw1;
        wv.z = lh * (1.f - lw)         * vh1 * vw0;
        wv.w = lh * lw                 * vh1 * vw1;

        int ih0 = min(max(h0, 0), Hc - 1);
        int ih1 = min(max(h1, 0), Hc - 1);
        int iw0 = min(max(w0, 0), Wc - 1);
        int iw1 = min(max(w1, 0), Wc - 1);

        metaW[e] = wv;
        metaI[e] = (uint32_t)(ih0 | (ih1 << 6) | (iw0 << 12) | (iw1 << 18));
    }

    const bool is_cons = (tid < NCONS);
    const float* Ag = g_wtf + (size_t)by * BM * CKc;

    // Consumer identity
    const int wid = tid >> 5;
    const int lane = tid & 31;
    const int warp_m = wid >> 2;       // 0..1 (consumers only)
    const int warp_n = wid & 3;        // 0..3
    const int r = lane >> 2;
    const int c4 = lane & 3;
    const uint32_t a_lane = (uint32_t)((warp_m * 64 + (lane & 15)) * ASTRB
                                       + ((lane & 16) ? 16 : 0));

    float acc[4][4][4];
#pragma unroll
    for (int i = 0; i < 4; ++i)
#pragma unroll
        for (int j = 0; j < 4; ++j)
#pragma unroll
            for (int q = 0; q < 4; ++q) acc[i][j][q] = 0.f;

    // A staging (consumers): 1024 float4 chunks, 4/thread
    auto issue_A = [&](int t) {
        const uint32_t abase = sbA + (t % ASTAGES) * ABYTES;
#pragma unroll
        for (int i = 0; i < 4; ++i) {
            int ch = tid + i * 256;
            int m = ch >> 3, k4 = ch & 7;
            cp_async16(abase + (uint32_t)(m * ASTRB + k4 * 16),
                       Ag + (size_t)m * CKc + t * BK + k4 * 4);
        }
    };

    // Producer: fill B tile t into buffer t&1.
    // Thread (wtid 0..63) handles p = 2*wtid, 2*wtid+1; loops 32 channels.
    auto fill_B = [&](int t) {
        const int wtid = tid - NCONS;
        const int k  = t >> 3;
        const int c0 = (t & 7) << 5;
        const int p  = wtid * 2;
        const int e  = (k << 7) + p;

        float4 wv0 = metaW[e];
        float4 wv1 = metaW[e + 1];
        uint32_t m0 = metaI[e];
        uint32_t m1 = metaI[e + 1];
        int a00 = ((m0 & 63) << 6)        + ((m0 >> 12) & 63);
        int a01 = ((m0 & 63) << 6)        + ((m0 >> 18) & 63);
        int a10 = (((m0 >> 6) & 63) << 6) + ((m0 >> 12) & 63);
        int a11 = (((m0 >> 6) & 63) << 6) + ((m0 >> 18) & 63);
        int b00 = ((m1 & 63) << 6)        + ((m1 >> 12) & 63);
        int b01 = ((m1 & 63) << 6)        + ((m1 >> 18) & 63);
        int b10 = (((m1 >> 6) & 63) << 6) + ((m1 >> 12) & 63);
        int b11 = (((m1 >> 6) & 63) << 6) + ((m1 >> 18) & 63);

        const float* xp = x + (((size_t)b * Cc + c0) << 12);
        float* bbuf = Bs + (t & 1) * (BBYTES / 4) + p;

#pragma unroll 4
        for (int c = 0; c < 32; ++c) {
            const float* xc = xp + (c << 12);
            float v0 = xc[a00] * wv0.x + xc[a01] * wv0.y
                     + xc[a10] * wv0.z + xc[a11] * wv0.w;
            float v1 = xc[b00] * wv1.x + xc[b01] * wv1.y
                     + xc[b10] * wv1.z + xc[b11] * wv1.w;
            uint2 pk = make_uint2(cvt_tf32(v0), cvt_tf32(v1));
            *(uint2*)(bbuf + c * BSTR) = pk;
        }
    };

    // ---- prologue ----
    __syncthreads();               // metadata visible
    if (is_cons) {
        issue_A(0); cp_commit();
        issue_A(1); cp_commit();
        cp_wait<1>();              // A(0) landed
    } else {
        fill_B(0);
    }
    __syncthreads();               // B(0) + A(0) visible to all

    for (int t = 0; t < NT; ++t) {
        if (is_cons) {
            if (t + 2 < NT) issue_A(t + 2);
            cp_commit();           // always commit -> exact group counting

            const uint32_t abase = sbA + (t % ASTAGES) * ABYTES + a_lane;
            const float* Bp = Bs + (t & 1) * (BBYTES / 4) + warp_n * 32;

#pragma unroll
            for (int kc = 0; kc < 4; ++kc) {
                uint32_t af[4][4];
#pragma unroll
                for (int mi = 0; mi < 4; ++mi)
                    ldmx4(abase + (uint32_t)(mi * 16 * ASTRB + kc * 32), af[mi]);

                const int kk = kc * 8;
                uint32_t bf[4][2];
#pragma unroll
                for (int ni = 0; ni < 4; ++ni) {
                    int n = ni * 8 + r;
                    bf[ni][0] = __float_as_uint(Bp[(kk + c4    ) * BSTR + n]);
                    bf[ni][1] = __float_as_uint(Bp[(kk + c4 + 4) * BSTR + n]);
                }
#pragma unroll
                for (int mi = 0; mi < 4; ++mi)
#pragma unroll
                    for (int ni = 0; ni < 4; ++ni)
                        mma_tf32(acc[mi][ni], af[mi][0], af[mi][1], af[mi][2], af[mi][3],
                                 bf[ni][0], bf[ni][1]);
            }
            cp_wait<1>();          // A(t+1) landed before the barrier
        } else {
            if (t + 1 < NT) fill_B(t + 1);
        }
        __syncthreads();
    }

    // ---- epilogue (consumers only) ----
    if (is_cons) {
        float* outb = out + ((size_t)b * OCc + by * BM) * Pc + (size_t)p0;
#pragma unroll
        for (int mi = 0; mi < 4; ++mi) {
            int oc0 = warp_m * 64 + mi * 16 + r;
#pragma unroll
            for (int ni = 0; ni < 4; ++ni) {
                int p = warp_n * 32 + ni * 8 + 2 * c4;
                float2 v0 = make_float2(acc[mi][ni][0], acc[mi][ni][1]);
                float2 v1 = make_float2(acc[mi][ni][2], acc[mi][ni][3]);
                *(float2*)(outb + (size_t) oc0      * Pc + p) = v0;
                *(float2*)(outb + (size_t)(oc0 + 8) * Pc + p) = v1;
            }
        }
    }
}

// ---------------------------------------------------------------------------
extern "C" void kernel_launch(void* const* d_in, const int* in_sizes, int n_in,
                              void* d_out, int out_size) {
    const float* x      = (const float*)d_in[0];
    const float* offset = (const float*)d_in[1];
    const float* weight = (const float*)d_in[2];
    float* out = (float*)d_out;

    cudaFuncSetAttribute(dcn_fused,
                         cudaFuncAttributeMaxDynamicSharedMemorySize, SM_TOTAL);

    round_weights<<<(OCc * CKc + 255) / 256, 256>>>(weight);

    dim3 grid(Pc / BN, OCc / BM, Bc);   // (32, 2, 4) = 256 CTAs, 2 per SM
    dcn_fused<<<grid, NTHREADS, SM_TOTAL>>>(x, offset, out);
}

// round 11
// speedup vs baseline: 2.1499x; 2.1499x over previous
#include <cuda_runtime.h>
#include <cstdint>

// Problem constants
#define Bc   4
#define Cc   256
#define Hc   64
#define Wc   64
#define OCc  256
#define Kc   9
#define Pc   4096
#define CKc  (Cc*Kc)    // 2304

__device__ float g_cols[(size_t)Bc * CKc * Pc];
__device__ float g_wtf[(size_t)OCc * CKc];      // tf32-rounded weights

__device__ __forceinline__ uint32_t cvt_tf32(float f) {
    uint32_t r;
    asm("cvt.rna.tf32.f32 %0, %1;" : "=r"(r) : "f"(f));
    return r;
}

// ---------------------------------------------------------------------------
// Stage 0+1 merged: blocks [0,288) do deformable im2col (2 positions/thread);
// blocks [288, 288+2304) round weights to tf32.
// ---------------------------------------------------------------------------
#define IM2COL_BLOCKS 288              // B*K*P / (256*2)
#define RW_BLOCKS     ((OCc * CKc) / 256)   // 2304

__global__ __launch_bounds__(256) void dcn_stage01(
    const float* __restrict__ x,
    const float* __restrict__ offset,
    const float* __restrict__ w)
{
    if (blockIdx.x >= IM2COL_BLOCKS) {
        int i = (blockIdx.x - IM2COL_BLOCKS) * 256 + threadIdx.x;
        g_wtf[i] = __uint_as_float(cvt_tf32(w[i]));
        return;
    }

    // pair index: each thread handles p = 2*p2, 2*p2+1 for one (b, k)
    int q  = blockIdx.x * 256 + threadIdx.x;     // < 73728
    int p2 = q & 2047;
    int k  = (q >> 11) % Kc;
    int b  = q / (2048 * Kc);
    int p  = p2 * 2;

    int ho = p >> 6;
    int wo = p & 63;
    int ki = k / 3;
    int kj = k - 3 * ki;

    const float* offb = offset + ((size_t)b * 18) * Pc;
    float2 dyv = *(const float2*)&offb[(2 * k    ) * Pc + p];
    float2 dxv = *(const float2*)&offb[(2 * k + 1) * Pc + p];

    // ---- metadata for the two positions ----
    float w0a, w1a, w2a, w3a, w0b, w1b, w2b, w3b;
    int i00a, i01a, i10a, i11a, i00b, i01b, i10b, i11b;
    {
        float ph = (float)(ho - 1 + ki) + dyv.x;
        float pw = (float)(wo - 1 + kj) + dxv.x;
        float h0f = floorf(ph), w0f = floorf(pw);
        float lh = ph - h0f, lw = pw - w0f;
        int h0 = (int)h0f, w0 = (int)w0f;
        int h1 = h0 + 1,   w1 = w0 + 1;
        float vh0 = (h0 >= 0 && h0 < Hc) ? 1.f : 0.f;
        float vh1 = (h1 >= 0 && h1 < Hc) ? 1.f : 0.f;
        float vw0 = (w0 >= 0 && w0 < Wc) ? 1.f : 0.f;
        float vw1 = (w1 >= 0 && w1 < Wc) ? 1.f : 0.f;
        w0a = (1.f - lh) * (1.f - lw) * vh0 * vw0;
        w1a = (1.f - lh) * lw         * vh0 * vw1;
        w2a = lh * (1.f - lw)         * vh1 * vw0;
        w3a = lh * lw                 * vh1 * vw1;
        int ih0 = min(max(h0, 0), Hc - 1);
        int ih1 = min(max(h1, 0), Hc - 1);
        int iw0 = min(max(w0, 0), Wc - 1);
        int iw1 = min(max(w1, 0), Wc - 1);
        i00a = ih0 * Wc + iw0; i01a = ih0 * Wc + iw1;
        i10a = ih1 * Wc + iw0; i11a = ih1 * Wc + iw1;
    }
    {
        // position p+1: wo+1 (p even, never wraps a row since 64 | row length
        // and p+1 stays in the same row: wo in [0,62] even)
        float ph = (float)(ho - 1 + ki) + dyv.y;
        float pw = (float)(wo + 1 - 1 + kj) + dxv.y;
        float h0f = floorf(ph), w0f = floorf(pw);
        float lh = ph - h0f, lw = pw - w0f;
        int h0 = (int)h0f, w0 = (int)w0f;
        int h1 = h0 + 1,   w1 = w0 + 1;
        float vh0 = (h0 >= 0 && h0 < Hc) ? 1.f : 0.f;
        float vh1 = (h1 >= 0 && h1 < Hc) ? 1.f : 0.f;
        float vw0 = (w0 >= 0 && w0 < Wc) ? 1.f : 0.f;
        float vw1 = (w1 >= 0 && w1 < Wc) ? 1.f : 0.f;
        w0b = (1.f - lh) * (1.f - lw) * vh0 * vw0;
        w1b = (1.f - lh) * lw         * vh0 * vw1;
        w2b = lh * (1.f - lw)         * vh1 * vw0;
        w3b = lh * lw                 * vh1 * vw1;
        int ih0 = min(max(h0, 0), Hc - 1);
        int ih1 = min(max(h1, 0), Hc - 1);
        int iw0 = min(max(w0, 0), Wc - 1);
        int iw1 = min(max(w1, 0), Wc - 1);
        i00b = ih0 * Wc + iw0; i01b = ih0 * Wc + iw1;
        i10b = ih1 * Wc + iw0; i11b = ih1 * Wc + iw1;
    }

    const float* xb = x + (size_t)b * Cc * Pc;
    float* colp = g_cols + (size_t)b * CKc * Pc + (size_t)k * Pc + p;

#pragma unroll 8
    for (int c = 0; c < Cc; ++c) {
        const float* xc = xb + (size_t)c * Pc;
        float va = __ldg(xc + i00a) * w0a + __ldg(xc + i01a) * w1a
                 + __ldg(xc + i10a) * w2a + __ldg(xc + i11a) * w3a;
        float vb = __ldg(xc + i00b) * w0b + __ldg(xc + i01b) * w1b
                 + __ldg(xc + i10b) * w2b + __ldg(xc + i11b) * w3b;
        uint2 pk = make_uint2(cvt_tf32(va), cvt_tf32(vb));
        *(uint2*)(colp + (size_t)c * (Kc * Pc)) = pk;
    }
}

// ---------------------------------------------------------------------------
// Stage 2: tf32 mma.sync GEMM (R9 verbatim). BM=128, BN=128, BK=32, 3 stages,
// 256 threads, 2 CTAs/SM. Warp grid 2(m) x 4(n), warp tile 64x32. B-fragment
// LDS software-pipelined across k8 chunks.
// ---------------------------------------------------------------------------
#define BM 128
#define BN 128
#define BK 32
#define NT (CKc / BK)      // 72
#define STAGES 3
#define ASTRB 144          // A smem row stride BYTES
#define ABYTES (BM * ASTRB)          // 18432
#define BSTR 136           // B smem row stride (words)
#define BBYTES (BK * BSTR * 4)       // 17408
#define SM_TOTAL (STAGES * (ABYTES + BBYTES))   // 107520

__device__ __forceinline__ uint32_t smem_u32(const void* p) {
    uint32_t a;
    asm("{ .reg .u64 t; cvta.to.shared.u64 t, %1; cvt.u32.u64 %0, t; }"
        : "=r"(a) : "l"(p));
    return a;
}
__device__ __forceinline__ void cp_async16(uint32_t dst, const void* src) {
    asm volatile("cp.async.cg.shared.global [%0], [%1], 16;"
                 :: "r"(dst), "l"(src) : "memory");
}
__device__ __forceinline__ void cp_commit() {
    asm volatile("cp.async.commit_group;" ::: "memory");
}
template <int N>
__device__ __forceinline__ void cp_wait() {
    asm volatile("cp.async.wait_group %0;" :: "n"(N) : "memory");
}
__device__ __forceinline__ void ldmx4(uint32_t addr, uint32_t r[4]) {
    asm volatile("ldmatrix.sync.aligned.m8n8.x4.shared.b16 {%0,%1,%2,%3}, [%4];"
                 : "=r"(r[0]), "=r"(r[1]), "=r"(r[2]), "=r"(r[3]) : "r"(addr));
}
__device__ __forceinline__ void mma_tf32(float c[4],
                                         uint32_t a0, uint32_t a1, uint32_t a2, uint32_t a3,
                                         uint32_t b0, uint32_t b1) {
    asm volatile(
        "mma.sync.aligned.m16n8k8.row.col.f32.tf32.tf32.f32 "
        "{%0,%1,%2,%3}, {%4,%5,%6,%7}, {%8,%9}, {%0,%1,%2,%3};"
        : "+f"(c[0]), "+f"(c[1]), "+f"(c[2]), "+f"(c[3])
        : "r"(a0), "r"(a1), "r"(a2), "r"(a3), "r"(b0), "r"(b1));
}

__global__ __launch_bounds__(256, 2) void dcn_gemm_mma(
    float* __restrict__ out)            // [B, OC, P]
{
    extern __shared__ float sm[];
    const uint32_t sbA = smem_u32(sm);
    const uint32_t sbB = sbA + STAGES * ABYTES;
    float* Bs = sm + (STAGES * ABYTES) / 4;

    const int tid = threadIdx.x;
    const int wid = tid >> 5;
    const int lane = tid & 31;
    const int warp_m = wid >> 2;
    const int warp_n = wid & 3;
    const int r = lane >> 2;
    const int c4 = lane & 3;

    const int bx = blockIdx.x;
    const int by = blockIdx.y;
    const int b  = blockIdx.z;

    const float* Ag = g_wtf + (size_t)by * BM * CKc;
    const float* Bg = g_cols + (size_t)b * CKc * Pc + (size_t)bx * BN;

    float acc[4][4][4];
#pragma unroll
    for (int i = 0; i < 4; ++i)
#pragma unroll
        for (int j = 0; j < 4; ++j)
#pragma unroll
            for (int q = 0; q < 4; ++q) acc[i][j][q] = 0.f;

    auto issue_tile = [&](int t) {
        const int buf = t % STAGES;
        const uint32_t abase = sbA + buf * ABYTES;
        const uint32_t bbase = sbB + buf * BBYTES;
#pragma unroll
        for (int i = 0; i < 4; ++i) {
            int ch = tid + i * 256;
            int m = ch >> 3, k4 = ch & 7;
            cp_async16(abase + (uint32_t)(m * ASTRB + k4 * 16),
                       Ag + (size_t)m * CKc + t * BK + k4 * 4);
        }
#pragma unroll
        for (int j = 0; j < 4; ++j) {
            int ch = tid + j * 256;
            int k = ch >> 5, n16 = ch & 31;
            cp_async16(bbase + (uint32_t)(k * (BSTR * 4) + n16 * 16),
                       Bg + (size_t)(t * BK + k) * Pc + n16 * 4);
        }
    };

#pragma unroll
    for (int s = 0; s < STAGES - 1; ++s) { issue_tile(s); cp_commit(); }

    const uint32_t a_lane = (uint32_t)((warp_m * 64 + (lane & 15)) * ASTRB
                                       + ((lane & 16) ? 16 : 0));

    for (int t = 0; t < NT; ++t) {
        const int buf = t % STAGES;
        cp_wait<STAGES - 2>();
        __syncthreads();

        if (t + STAGES - 1 < NT) issue_tile(t + STAGES - 1);
        cp_commit();

        const uint32_t abase = sbA + buf * ABYTES + a_lane;
        const float* Bp = Bs + buf * (BBYTES / 4) + warp_n * 32;

        uint32_t bcur[4][2], bnxt[4][2];
#pragma unroll
        for (int ni = 0; ni < 4; ++ni) {
            int n = ni * 8 + r;
            bcur[ni][0] = __float_as_uint(Bp[(c4    ) * BSTR + n]);
            bcur[ni][1] = __float_as_uint(Bp[(c4 + 4) * BSTR + n]);
        }

#pragma unroll
        for (int kc = 0; kc < 4; ++kc) {
            uint32_t af[4][4];
#pragma unroll
            for (int mi = 0; mi < 4; ++mi)
                ldmx4(abase + (uint32_t)(mi * 16 * ASTRB + kc * 32), af[mi]);

            if (kc < 3) {
                const int kk = (kc + 1) * 8;
#pragma unroll
                for (int ni = 0; ni < 4; ++ni) {
                    int n = ni * 8 + r;
                    bnxt[ni][0] = __float_as_uint(Bp[(kk + c4    ) * BSTR + n]);
                    bnxt[ni][1] = __float_as_uint(Bp[(kk + c4 + 4) * BSTR + n]);
                }
            }

#pragma unroll
            for (int mi = 0; mi < 4; ++mi)
#pragma unroll
                for (int ni = 0; ni < 4; ++ni)
                    mma_tf32(acc[mi][ni], af[mi][0], af[mi][1], af[mi][2], af[mi][3],
                             bcur[ni][0], bcur[ni][1]);

#pragma unroll
            for (int ni = 0; ni < 4; ++ni) {
                bcur[ni][0] = bnxt[ni][0];
                bcur[ni][1] = bnxt[ni][1];
            }
        }
    }

    float* outb = out + ((size_t)b * OCc + by * BM) * Pc + (size_t)bx * BN;
#pragma unroll
    for (int mi = 0; mi < 4; ++mi) {
        int oc0 = warp_m * 64 + mi * 16 + r;
#pragma unroll
        for (int ni = 0; ni < 4; ++ni) {
            int p = warp_n * 32 + ni * 8 + 2 * c4;
            float2 v0 = make_float2(acc[mi][ni][0], acc[mi][ni][1]);
            float2 v1 = make_float2(acc[mi][ni][2], acc[mi][ni][3]);
            *(float2*)(outb + (size_t) oc0      * Pc + p) = v0;
            *(float2*)(outb + (size_t)(oc0 + 8) * Pc + p) = v1;
        }
    }
}

// ---------------------------------------------------------------------------
extern "C" void kernel_launch(void* const* d_in, const int* in_sizes, int n_in,
                              void* d_out, int out_size) {
    const float* x      = (const float*)d_in[0];
    const float* offset = (const float*)d_in[1];
    const float* weight = (const float*)d_in[2];
    float* out = (float*)d_out;

    cudaFuncSetAttribute(dcn_gemm_mma,
                         cudaFuncAttributeMaxDynamicSharedMemorySize, SM_TOTAL);

    dcn_stage01<<<IM2COL_BLOCKS + RW_BLOCKS, 256>>>(x, offset, weight);

    dim3 grid(Pc / BN, OCc / BM, Bc);   // (32, 2, 4) = 256 CTAs, 2 per SM
    dcn_gemm_mma<<<grid, 256, SM_TOTAL>>>(out);
}

// round 12
// speedup vs baseline: 2.1640x; 1.0065x over previous
#include <cuda_runtime.h>
#include <cstdint>

// Problem constants
#define Bc   4
#define Cc   256
#define Hc   64
#define Wc   64
#define OCc  256
#define Kc   9
#define Pc   4096
#define CKc  (Cc*Kc)    // 2304

__device__ float g_cols[(size_t)Bc * CKc * Pc];
__device__ float g_wtf[(size_t)OCc * CKc];      // tf32-rounded weights

__device__ __forceinline__ uint32_t cvt_tf32(float f) {
    uint32_t r;
    asm("cvt.rna.tf32.f32 %0, %1;" : "=r"(r) : "f"(f));
    return r;
}

// ---------------------------------------------------------------------------
// Stage 0+1 merged: blocks [0,288) do deformable im2col (2 positions/thread);
// blocks [288, 288+2304) round weights to tf32.
// ---------------------------------------------------------------------------
#define IM2COL_BLOCKS 288              // B*K*P / (256*2)
#define RW_BLOCKS     ((OCc * CKc) / 256)   // 2304

__global__ __launch_bounds__(256) void dcn_stage01(
    const float* __restrict__ x,
    const float* __restrict__ offset,
    const float* __restrict__ w)
{
    if (blockIdx.x >= IM2COL_BLOCKS) {
        int i = (blockIdx.x - IM2COL_BLOCKS) * 256 + threadIdx.x;
        g_wtf[i] = __uint_as_float(cvt_tf32(w[i]));
        return;
    }

    // pair index: each thread handles p = 2*p2, 2*p2+1 for one (b, k)
    int q  = blockIdx.x * 256 + threadIdx.x;     // < 73728
    int p2 = q & 2047;
    int k  = (q >> 11) % Kc;
    int b  = q / (2048 * Kc);
    int p  = p2 * 2;

    int ho = p >> 6;
    int wo = p & 63;
    int ki = k / 3;
    int kj = k - 3 * ki;

    const float* offb = offset + ((size_t)b * 18) * Pc;
    float2 dyv = *(const float2*)&offb[(2 * k    ) * Pc + p];
    float2 dxv = *(const float2*)&offb[(2 * k + 1) * Pc + p];

    // ---- metadata for the two positions ----
    float w0a, w1a, w2a, w3a, w0b, w1b, w2b, w3b;
    int i00a, i01a, i10a, i11a, i00b, i01b, i10b, i11b;
    {
        float ph = (float)(ho - 1 + ki) + dyv.x;
        float pw = (float)(wo - 1 + kj) + dxv.x;
        float h0f = floorf(ph), w0f = floorf(pw);
        float lh = ph - h0f, lw = pw - w0f;
        int h0 = (int)h0f, w0 = (int)w0f;
        int h1 = h0 + 1,   w1 = w0 + 1;
        float vh0 = (h0 >= 0 && h0 < Hc) ? 1.f : 0.f;
        float vh1 = (h1 >= 0 && h1 < Hc) ? 1.f : 0.f;
        float vw0 = (w0 >= 0 && w0 < Wc) ? 1.f : 0.f;
        float vw1 = (w1 >= 0 && w1 < Wc) ? 1.f : 0.f;
        w0a = (1.f - lh) * (1.f - lw) * vh0 * vw0;
        w1a = (1.f - lh) * lw         * vh0 * vw1;
        w2a = lh * (1.f - lw)         * vh1 * vw0;
        w3a = lh * lw                 * vh1 * vw1;
        int ih0 = min(max(h0, 0), Hc - 1);
        int ih1 = min(max(h1, 0), Hc - 1);
        int iw0 = min(max(w0, 0), Wc - 1);
        int iw1 = min(max(w1, 0), Wc - 1);
        i00a = ih0 * Wc + iw0; i01a = ih0 * Wc + iw1;
        i10a = ih1 * Wc + iw0; i11a = ih1 * Wc + iw1;
    }
    {
        // position p+1: wo+1 (p even, never wraps a row since 64 | row length
        // and p+1 stays in the same row: wo in [0,62] even)
        float ph = (float)(ho - 1 + ki) + dyv.y;
        float pw = (float)(wo + 1 - 1 + kj) + dxv.y;
        float h0f = floorf(ph), w0f = floorf(pw);
        float lh = ph - h0f, lw = pw - w0f;
        int h0 = (int)h0f, w0 = (int)w0f;
        int h1 = h0 + 1,   w1 = w0 + 1;
        float vh0 = (h0 >= 0 && h0 < Hc) ? 1.f : 0.f;
        float vh1 = (h1 >= 0 && h1 < Hc) ? 1.f : 0.f;
        float vw0 = (w0 >= 0 && w0 < Wc) ? 1.f : 0.f;
        float vw1 = (w1 >= 0 && w1 < Wc) ? 1.f : 0.f;
        w0b = (1.f - lh) * (1.f - lw) * vh0 * vw0;
        w1b = (1.f - lh) * lw         * vh0 * vw1;
        w2b = lh * (1.f - lw)         * vh1 * vw0;
        w3b = lh * lw                 * vh1 * vw1;
        int ih0 = min(max(h0, 0), Hc - 1);
        int ih1 = min(max(h1, 0), Hc - 1);
        int iw0 = min(max(w0, 0), Wc - 1);
        int iw1 = min(max(w1, 0), Wc - 1);
        i00b = ih0 * Wc + iw0; i01b = ih0 * Wc + iw1;
        i10b = ih1 * Wc + iw0; i11b = ih1 * Wc + iw1;
    }

    const float* xb = x + (size_t)b * Cc * Pc;
    float* colp = g_cols + (size_t)b * CKc * Pc + (size_t)k * Pc + p;

#pragma unroll 8
    for (int c = 0; c < Cc; ++c) {
        const float* xc = xb + (size_t)c * Pc;
        float va = __ldg(xc + i00a) * w0a + __ldg(xc + i01a) * w1a
                 + __ldg(xc + i10a) * w2a + __ldg(xc + i11a) * w3a;
        float vb = __ldg(xc + i00b) * w0b + __ldg(xc + i01b) * w1b
                 + __ldg(xc + i10b) * w2b + __ldg(xc + i11b) * w3b;
        uint2 pk = make_uint2(cvt_tf32(va), cvt_tf32(vb));
        *(uint2*)(colp + (size_t)c * (Kc * Pc)) = pk;
    }
}

// ---------------------------------------------------------------------------
// Stage 2: tf32 mma.sync GEMM (R9 verbatim). BM=128, BN=128, BK=32, 3 stages,
// 256 threads, 2 CTAs/SM. Warp grid 2(m) x 4(n), warp tile 64x32. B-fragment
// LDS software-pipelined across k8 chunks.
// ---------------------------------------------------------------------------
#define BM 128
#define BN 128
#define BK 32
#define NT (CKc / BK)      // 72
#define STAGES 3
#define ASTRB 144          // A smem row stride BYTES
#define ABYTES (BM * ASTRB)          // 18432
#define BSTR 136           // B smem row stride (words)
#define BBYTES (BK * BSTR * 4)       // 17408
#define SM_TOTAL (STAGES * (ABYTES + BBYTES))   // 107520

__device__ __forceinline__ uint32_t smem_u32(const void* p) {
    uint32_t a;
    asm("{ .reg .u64 t; cvta.to.shared.u64 t, %1; cvt.u32.u64 %0, t; }"
        : "=r"(a) : "l"(p));
    return a;
}
__device__ __forceinline__ void cp_async16(uint32_t dst, const void* src) {
    asm volatile("cp.async.cg.shared.global [%0], [%1], 16;"
                 :: "r"(dst), "l"(src) : "memory");
}
__device__ __forceinline__ void cp_commit() {
    asm volatile("cp.async.commit_group;" ::: "memory");
}
template <int N>
__device__ __forceinline__ void cp_wait() {
    asm volatile("cp.async.wait_group %0;" :: "n"(N) : "memory");
}
__device__ __forceinline__ void ldmx4(uint32_t addr, uint32_t r[4]) {
    asm volatile("ldmatrix.sync.aligned.m8n8.x4.shared.b16 {%0,%1,%2,%3}, [%4];"
                 : "=r"(r[0]), "=r"(r[1]), "=r"(r[2]), "=r"(r[3]) : "r"(addr));
}
__device__ __forceinline__ void mma_tf32(float c[4],
                                         uint32_t a0, uint32_t a1, uint32_t a2, uint32_t a3,
                                         uint32_t b0, uint32_t b1) {
    asm volatile(
        "mma.sync.aligned.m16n8k8.row.col.f32.tf32.tf32.f32 "
        "{%0,%1,%2,%3}, {%4,%5,%6,%7}, {%8,%9}, {%0,%1,%2,%3};"
        : "+f"(c[0]), "+f"(c[1]), "+f"(c[2]), "+f"(c[3])
        : "r"(a0), "r"(a1), "r"(a2), "r"(a3), "r"(b0), "r"(b1));
}

__global__ __launch_bounds__(256, 2) void dcn_gemm_mma(
    float* __restrict__ out)            // [B, OC, P]
{
    extern __shared__ float sm[];
    const uint32_t sbA = smem_u32(sm);
    const uint32_t sbB = sbA + STAGES * ABYTES;
    float* Bs = sm + (STAGES * ABYTES) / 4;

    const int tid = threadIdx.x;
    const int wid = tid >> 5;
    const int lane = tid & 31;
    const int warp_m = wid >> 2;
    const int warp_n = wid & 3;
    const int r = lane >> 2;
    const int c4 = lane & 3;

    const int bx = blockIdx.x;
    const int by = blockIdx.y;
    const int b  = blockIdx.z;

    const float* Ag = g_wtf + (size_t)by * BM * CKc;
    const float* Bg = g_cols + (size_t)b * CKc * Pc + (size_t)bx * BN;

    float acc[4][4][4];
#pragma unroll
    for (int i = 0; i < 4; ++i)
#pragma unroll
        for (int j = 0; j < 4; ++j)
#pragma unroll
            for (int q = 0; q < 4; ++q) acc[i][j][q] = 0.f;

    auto issue_tile = [&](int t) {
        const int buf = t % STAGES;
        const uint32_t abase = sbA + buf * ABYTES;
        const uint32_t bbase = sbB + buf * BBYTES;
#pragma unroll
        for (int i = 0; i < 4; ++i) {
            int ch = tid + i * 256;
            int m = ch >> 3, k4 = ch & 7;
            cp_async16(abase + (uint32_t)(m * ASTRB + k4 * 16),
                       Ag + (size_t)m * CKc + t * BK + k4 * 4);
        }
#pragma unroll
        for (int j = 0; j < 4; ++j) {
            int ch = tid + j * 256;
            int k = ch >> 5, n16 = ch & 31;
            cp_async16(bbase + (uint32_t)(k * (BSTR * 4) + n16 * 16),
                       Bg + (size_t)(t * BK + k) * Pc + n16 * 4);
        }
    };

#pragma unroll
    for (int s = 0; s < STAGES - 1; ++s) { issue_tile(s); cp_commit(); }

    const uint32_t a_lane = (uint32_t)((warp_m * 64 + (lane & 15)) * ASTRB
                                       + ((lane & 16) ? 16 : 0));

    for (int t = 0; t < NT; ++t) {
        const int buf = t % STAGES;
        cp_wait<STAGES - 2>();
        __syncthreads();

        if (t + STAGES - 1 < NT) issue_tile(t + STAGES - 1);
        cp_commit();

        const uint32_t abase = sbA + buf * ABYTES + a_lane;
        const float* Bp = Bs + buf * (BBYTES / 4) + warp_n * 32;

        uint32_t bcur[4][2], bnxt[4][2];
#pragma unroll
        for (int ni = 0; ni < 4; ++ni) {
            int n = ni * 8 + r;
            bcur[ni][0] = __float_as_uint(Bp[(c4    ) * BSTR + n]);
            bcur[ni][1] = __float_as_uint(Bp[(c4 + 4) * BSTR + n]);
        }

#pragma unroll
        for (int kc = 0; kc < 4; ++kc) {
            uint32_t af[4][4];
#pragma unroll
            for (int mi = 0; mi < 4; ++mi)
                ldmx4(abase + (uint32_t)(mi * 16 * ASTRB + kc * 32), af[mi]);

            if (kc < 3) {
                const int kk = (kc + 1) * 8;
#pragma unroll
                for (int ni = 0; ni < 4; ++ni) {
                    int n = ni * 8 + r;
                    bnxt[ni][0] = __float_as_uint(Bp[(kk + c4    ) * BSTR + n]);
                    bnxt[ni][1] = __float_as_uint(Bp[(kk + c4 + 4) * BSTR + n]);
                }
            }

#pragma unroll
            for (int mi = 0; mi < 4; ++mi)
#pragma unroll
                for (int ni = 0; ni < 4; ++ni)
                    mma_tf32(acc[mi][ni], af[mi][0], af[mi][1], af[mi][2], af[mi][3],
                             bcur[ni][0], bcur[ni][1]);

#pragma unroll
            for (int ni = 0; ni < 4; ++ni) {
                bcur[ni][0] = bnxt[ni][0];
                bcur[ni][1] = bnxt[ni][1];
            }
        }
    }

    float* outb = out + ((size_t)b * OCc + by * BM) * Pc + (size_t)bx * BN;
#pragma unroll
    for (int mi = 0; mi < 4; ++mi) {
        int oc0 = warp_m * 64 + mi * 16 + r;
#pragma unroll
        for (int ni = 0; ni < 4; ++ni) {
            int p = warp_n * 32 + ni * 8 + 2 * c4;
            float2 v0 = make_float2(acc[mi][ni][0], acc[mi][ni][1]);
            float2 v1 = make_float2(acc[mi][ni][2], acc[mi][ni][3]);
            *(float2*)(outb + (size_t) oc0      * Pc + p) = v0;
            *(float2*)(outb + (size_t)(oc0 + 8) * Pc + p) = v1;
        }
    }
}

// ---------------------------------------------------------------------------
extern "C" void kernel_launch(void* const* d_in, const int* in_sizes, int n_in,
                              void* d_out, int out_size) {
    const float* x      = (const float*)d_in[0];
    const float* offset = (const float*)d_in[1];
    const float* weight = (const float*)d_in[2];
    float* out = (float*)d_out;

    cudaFuncSetAttribute(dcn_gemm_mma,
                         cudaFuncAttributeMaxDynamicSharedMemorySize, SM_TOTAL);

    dcn_stage01<<<IM2COL_BLOCKS + RW_BLOCKS, 256>>>(x, offset, weight);

    dim3 grid(Pc / BN, OCc / BM, Bc);   // (32, 2, 4) = 256 CTAs, 2 per SM
    dcn_gemm_mma<<<grid, 256, SM_TOTAL>>>(out);
}

// round 13
// speedup vs baseline: 2.3807x; 1.1002x over previous
#include <cuda_runtime.h>
#include <cstdint>

// Problem constants
#define Bc   4
#define Cc   256
#define Hc   64
#define Wc   64
#define OCc  256
#define Kc   9
#define Pc   4096
#define CKc  (Cc*Kc)    // 2304

__device__ float g_cols[(size_t)Bc * CKc * Pc];
__device__ float g_wtf[(size_t)OCc * CKc];      // tf32-rounded weights

__device__ __forceinline__ uint32_t cvt_tf32(float f) {
    uint32_t r;
    asm("cvt.rna.tf32.f32 %0, %1;" : "=r"(r) : "f"(f));
    return r;
}

// ---------------------------------------------------------------------------
// Stage 0+1 merged.
// im2col blocks [0,576): thread = (b, k, c-half, p-pair); handles 2 adjacent
// positions x 128 channels -> STG.64 stores, float2 offset loads, same warp
// count as R9 (147456 threads).
// Blocks [576, 576+2304): round weights to tf32.
// ---------------------------------------------------------------------------
#define IM2COL_BLOCKS 576
#define RW_BLOCKS     ((OCc * CKc) / 256)   // 2304

__global__ __launch_bounds__(256) void dcn_stage01(
    const float* __restrict__ x,
    const float* __restrict__ offset,
    const float* __restrict__ w)
{
    if (blockIdx.x >= IM2COL_BLOCKS) {
        int i = (blockIdx.x - IM2COL_BLOCKS) * 256 + threadIdx.x;
        g_wtf[i] = __uint_as_float(cvt_tf32(w[i]));
        return;
    }

    int q  = blockIdx.x * 256 + threadIdx.x;     // < 147456
    int p2 = q & 2047;                           // position pair
    int ch = (q >> 11) & 1;                      // channel half
    int k  = (q >> 12) % Kc;
    int b  = q / (4096 * Kc);
    int p  = p2 * 2;

    int ho = p >> 6;
    int wo = p & 63;                             // even, p+1 same row
    int ki = k / 3;
    int kj = k - 3 * ki;

    const float* offb = offset + ((size_t)b * 18) * Pc;
    float2 dyv = *(const float2*)&offb[(2 * k    ) * Pc + p];
    float2 dxv = *(const float2*)&offb[(2 * k + 1) * Pc + p];

    float w0a, w1a, w2a, w3a, w0b, w1b, w2b, w3b;
    int i00a, i01a, i10a, i11a, i00b, i01b, i10b, i11b;
    {
        float ph = (float)(ho - 1 + ki) + dyv.x;
        float pw = (float)(wo - 1 + kj) + dxv.x;
        float h0f = floorf(ph), w0f = floorf(pw);
        float lh = ph - h0f, lw = pw - w0f;
        int h0 = (int)h0f, w0 = (int)w0f;
        int h1 = h0 + 1,   w1 = w0 + 1;
        float vh0 = (h0 >= 0 && h0 < Hc) ? 1.f : 0.f;
        float vh1 = (h1 >= 0 && h1 < Hc) ? 1.f : 0.f;
        float vw0 = (w0 >= 0 && w0 < Wc) ? 1.f : 0.f;
        float vw1 = (w1 >= 0 && w1 < Wc) ? 1.f : 0.f;
        w0a = (1.f - lh) * (1.f - lw) * vh0 * vw0;
        w1a = (1.f - lh) * lw         * vh0 * vw1;
        w2a = lh * (1.f - lw)         * vh1 * vw0;
        w3a = lh * lw                 * vh1 * vw1;
        int ih0 = min(max(h0, 0), Hc - 1);
        int ih1 = min(max(h1, 0), Hc - 1);
        int iw0 = min(max(w0, 0), Wc - 1);
        int iw1 = min(max(w1, 0), Wc - 1);
        i00a = ih0 * Wc + iw0; i01a = ih0 * Wc + iw1;
        i10a = ih1 * Wc + iw0; i11a = ih1 * Wc + iw1;
    }
    {
        float ph = (float)(ho - 1 + ki) + dyv.y;
        float pw = (float)(wo + kj) + dxv.y;     // (wo+1) - 1 + kj
        float h0f = floorf(ph), w0f = floorf(pw);
        float lh = ph - h0f, lw = pw - w0f;
        int h0 = (int)h0f, w0 = (int)w0f;
        int h1 = h0 + 1,   w1 = w0 + 1;
        float vh0 = (h0 >= 0 && h0 < Hc) ? 1.f : 0.f;
        float vh1 = (h1 >= 0 && h1 < Hc) ? 1.f : 0.f;
        float vw0 = (w0 >= 0 && w0 < Wc) ? 1.f : 0.f;
        float vw1 = (w1 >= 0 && w1 < Wc) ? 1.f : 0.f;
        w0b = (1.f - lh) * (1.f - lw) * vh0 * vw0;
        w1b = (1.f - lh) * lw         * vh0 * vw1;
        w2b = lh * (1.f - lw)         * vh1 * vw0;
        w3b = lh * lw                 * vh1 * vw1;
        int ih0 = min(max(h0, 0), Hc - 1);
        int ih1 = min(max(h1, 0), Hc - 1);
        int iw0 = min(max(w0, 0), Wc - 1);
        int iw1 = min(max(w1, 0), Wc - 1);
        i00b = ih0 * Wc + iw0; i01b = ih0 * Wc + iw1;
        i10b = ih1 * Wc + iw0; i11b = ih1 * Wc + iw1;
    }

    const float* xb = x + ((size_t)b * Cc + ch * 128) * Pc;
    float* colp = g_cols + (size_t)b * CKc * Pc
                + ((size_t)(ch * 128) * Kc + k) * Pc + p;

#pragma unroll 4
    for (int cc = 0; cc < 128; ++cc) {
        const float* xc = xb + (size_t)cc * Pc;
        float va = __ldg(xc + i00a) * w0a + __ldg(xc + i01a) * w1a
                 + __ldg(xc + i10a) * w2a + __ldg(xc + i11a) * w3a;
        float vb = __ldg(xc + i00b) * w0b + __ldg(xc + i01b) * w1b
                 + __ldg(xc + i10b) * w2b + __ldg(xc + i11b) * w3b;
        uint2 pk = make_uint2(cvt_tf32(va), cvt_tf32(vb));
        *(uint2*)(colp + (size_t)cc * (Kc * Pc)) = pk;
    }
}

// ---------------------------------------------------------------------------
// Stage 2: tf32 mma.sync GEMM (R9 verbatim, proven 121.6us).
// ---------------------------------------------------------------------------
#define BM 128
#define BN 128
#define BK 32
#define NT (CKc / BK)      // 72
#define STAGES 3
#define ASTRB 144
#define ABYTES (BM * ASTRB)          // 18432
#define BSTR 136
#define BBYTES (BK * BSTR * 4)       // 17408
#define SM_TOTAL (STAGES * (ABYTES + BBYTES))   // 107520

__device__ __forceinline__ uint32_t smem_u32(const void* p) {
    uint32_t a;
    asm("{ .reg .u64 t; cvta.to.shared.u64 t, %1; cvt.u32.u64 %0, t; }"
        : "=r"(a) : "l"(p));
    return a;
}
__device__ __forceinline__ void cp_async16(uint32_t dst, const void* src) {
    asm volatile("cp.async.cg.shared.global [%0], [%1], 16;"
                 :: "r"(dst), "l"(src) : "memory");
}
__device__ __forceinline__ void cp_commit() {
    asm volatile("cp.async.commit_group;" ::: "memory");
}
template <int N>
__device__ __forceinline__ void cp_wait() {
    asm volatile("cp.async.wait_group %0;" :: "n"(N) : "memory");
}
__device__ __forceinline__ void ldmx4(uint32_t addr, uint32_t r[4]) {
    asm volatile("ldmatrix.sync.aligned.m8n8.x4.shared.b16 {%0,%1,%2,%3}, [%4];"
                 : "=r"(r[0]), "=r"(r[1]), "=r"(r[2]), "=r"(r[3]) : "r"(addr));
}
__device__ __forceinline__ void mma_tf32(float c[4],
                                         uint32_t a0, uint32_t a1, uint32_t a2, uint32_t a3,
                                         uint32_t b0, uint32_t b1) {
    asm volatile(
        "mma.sync.aligned.m16n8k8.row.col.f32.tf32.tf32.f32 "
        "{%0,%1,%2,%3}, {%4,%5,%6,%7}, {%8,%9}, {%0,%1,%2,%3};"
        : "+f"(c[0]), "+f"(c[1]), "+f"(c[2]), "+f"(c[3])
        : "r"(a0), "r"(a1), "r"(a2), "r"(a3), "r"(b0), "r"(b1));
}

__global__ __launch_bounds__(256, 2) void dcn_gemm_mma(
    float* __restrict__ out)            // [B, OC, P]
{
    extern __shared__ float sm[];
    const uint32_t sbA = smem_u32(sm);
    const uint32_t sbB = sbA + STAGES * ABYTES;
    float* Bs = sm + (STAGES * ABYTES) / 4;

    const int tid = threadIdx.x;
    const int wid = tid >> 5;
    const int lane = tid & 31;
    const int warp_m = wid >> 2;
    const int warp_n = wid & 3;
    const int r = lane >> 2;
    const int c4 = lane & 3;

    const int bx = blockIdx.x;
    const int by = blockIdx.y;
    const int b  = blockIdx.z;

    const float* Ag = g_wtf + (size_t)by * BM * CKc;
    const float* Bg = g_cols + (size_t)b * CKc * Pc + (size_t)bx * BN;

    float acc[4][4][4];
#pragma unroll
    for (int i = 0; i < 4; ++i)
#pragma unroll
        for (int j = 0; j < 4; ++j)
#pragma unroll
            for (int q = 0; q < 4; ++q) acc[i][j][q] = 0.f;

    auto issue_tile = [&](int t) {
        const int buf = t % STAGES;
        const uint32_t abase = sbA + buf * ABYTES;
        const uint32_t bbase = sbB + buf * BBYTES;
#pragma unroll
        for (int i = 0; i < 4; ++i) {
            int ch = tid + i * 256;
            int m = ch >> 3, k4 = ch & 7;
            cp_async16(abase + (uint32_t)(m * ASTRB + k4 * 16),
                       Ag + (size_t)m * CKc + t * BK + k4 * 4);
        }
#pragma unroll
        for (int j = 0; j < 4; ++j) {
            int ch = tid + j * 256;
            int k = ch >> 5, n16 = ch & 31;
            cp_async16(bbase + (uint32_t)(k * (BSTR * 4) + n16 * 16),
                       Bg + (size_t)(t * BK + k) * Pc + n16 * 4);
        }
    };

#pragma unroll
    for (int s = 0; s < STAGES - 1; ++s) { issue_tile(s); cp_commit(); }

    const uint32_t a_lane = (uint32_t)((warp_m * 64 + (lane & 15)) * ASTRB
                                       + ((lane & 16) ? 16 : 0));

    for (int t = 0; t < NT; ++t) {
        const int buf = t % STAGES;
        cp_wait<STAGES - 2>();
        __syncthreads();

        if (t + STAGES - 1 < NT) issue_tile(t + STAGES - 1);
        cp_commit();

        const uint32_t abase = sbA + buf * ABYTES + a_lane;
        const float* Bp = Bs + buf * (BBYTES / 4) + warp_n * 32;

        uint32_t bcur[4][2], bnxt[4][2];
#pragma unroll
        for (int ni = 0; ni < 4; ++ni) {
            int n = ni * 8 + r;
            bcur[ni][0] = __float_as_uint(Bp[(c4    ) * BSTR + n]);
            bcur[ni][1] = __float_as_uint(Bp[(c4 + 4) * BSTR + n]);
        }

#pragma unroll
        for (int kc = 0; kc < 4; ++kc) {
            uint32_t af[4][4];
#pragma unroll
            for (int mi = 0; mi < 4; ++mi)
                ldmx4(abase + (uint32_t)(mi * 16 * ASTRB + kc * 32), af[mi]);

            if (kc < 3) {
                const int kk = (kc + 1) * 8;
#pragma unroll
                for (int ni = 0; ni < 4; ++ni) {
                    int n = ni * 8 + r;
                    bnxt[ni][0] = __float_as_uint(Bp[(kk + c4    ) * BSTR + n]);
                    bnxt[ni][1] = __float_as_uint(Bp[(kk + c4 + 4) * BSTR + n]);
                }
            }

#pragma unroll
            for (int mi = 0; mi < 4; ++mi)
#pragma unroll
                for (int ni = 0; ni < 4; ++ni)
                    mma_tf32(acc[mi][ni], af[mi][0], af[mi][1], af[mi][2], af[mi][3],
                             bcur[ni][0], bcur[ni][1]);

#pragma unroll
            for (int ni = 0; ni < 4; ++ni) {
                bcur[ni][0] = bnxt[ni][0];
                bcur[ni][1] = bnxt[ni][1];
            }
        }
    }

    float* outb = out + ((size_t)b * OCc + by * BM) * Pc + (size_t)bx * BN;
#pragma unroll
    for (int mi = 0; mi < 4; ++mi) {
        int oc0 = warp_m * 64 + mi * 16 + r;
#pragma unroll
        for (int ni = 0; ni < 4; ++ni) {
            int p = warp_n * 32 + ni * 8 + 2 * c4;
            float2 v0 = make_float2(acc[mi][ni][0], acc[mi][ni][1]);
            float2 v1 = make_float2(acc[mi][ni][2], acc[mi][ni][3]);
            *(float2*)(outb + (size_t) oc0      * Pc + p) = v0;
            *(float2*)(outb + (size_t)(oc0 + 8) * Pc + p) = v1;
        }
    }
}

// ---------------------------------------------------------------------------
extern "C" void kernel_launch(void* const* d_in, const int* in_sizes, int n_in,
                              void* d_out, int out_size) {
    const float* x      = (const float*)d_in[0];
    const float* offset = (const float*)d_in[1];
    const float* weight = (const float*)d_in[2];
    float* out = (float*)d_out;

    cudaFuncSetAttribute(dcn_gemm_mma,
                         cudaFuncAttributeMaxDynamicSharedMemorySize, SM_TOTAL);

    dcn_stage01<<<IM2COL_BLOCKS + RW_BLOCKS, 256>>>(x, offset, weight);

    dim3 grid(Pc / BN, OCc / BM, Bc);   // (32, 2, 4) = 256 CTAs, 2 per SM
    dcn_gemm_mma<<<grid, 256, SM_TOTAL>>>(out);
}

// round 15
// speedup vs baseline: 2.5838x; 1.0853x over previous
#include <cuda_runtime.h>
#include <cstdint>

// Problem constants
#define Bc   4
#define Cc   256
#define Hc   64
#define Wc   64
#define OCc  256
#define Kc   9
#define Pc   4096
#define CKc  (Cc*Kc)    // 2304

__device__ float g_cols[(size_t)Bc * CKc * Pc];
__device__ float g_wtf[(size_t)OCc * CKc];      // tf32-rounded weights

__device__ __forceinline__ uint32_t cvt_tf32(float f) {
    uint32_t r;
    asm("cvt.rna.tf32.f32 %0, %1;" : "=r"(r) : "f"(f));
    return r;
}

// ---------------------------------------------------------------------------
// Stage 0+1 merged: blocks [0,576) do deformable im2col; blocks [576,2880)
// round weights to tf32.  (R9 structure; unroll bumped to 8.)
// ---------------------------------------------------------------------------
#define IM2COL_BLOCKS 576              // B*K*P / 256
#define RW_BLOCKS     ((OCc * CKc) / 256)   // 2304

__global__ __launch_bounds__(256) void dcn_stage01(
    const float* __restrict__ x,
    const float* __restrict__ offset,
    const float* __restrict__ w)
{
    if (blockIdx.x >= IM2COL_BLOCKS) {
        int i = (blockIdx.x - IM2COL_BLOCKS) * 256 + threadIdx.x;
        g_wtf[i] = __uint_as_float(cvt_tf32(w[i]));
        return;
    }

    int tid = blockIdx.x * 256 + threadIdx.x;
    int p = tid & (Pc - 1);
    int k = (tid >> 12) % Kc;
    int b = tid / (Pc * Kc);

    int ho = p >> 6;
    int wo = p & 63;
    int ki = k / 3;
    int kj = k - 3 * ki;

    const float* offb = offset + ((size_t)b * 18) * Pc;
    float dy = offb[(2 * k    ) * Pc + p];
    float dx = offb[(2 * k + 1) * Pc + p];

    float ph = (float)(ho - 1 + ki) + dy;
    float pw = (float)(wo - 1 + kj) + dx;

    float h0f = floorf(ph), w0f = floorf(pw);
    float lh = ph - h0f,    lw = pw - w0f;
    int h0 = (int)h0f, w0 = (int)w0f;
    int h1 = h0 + 1,   w1 = w0 + 1;

    float vh0 = (h0 >= 0 && h0 < Hc) ? 1.f : 0.f;
    float vh1 = (h1 >= 0 && h1 < Hc) ? 1.f : 0.f;
    float vw0 = (w0 >= 0 && w0 < Wc) ? 1.f : 0.f;
    float vw1 = (w1 >= 0 && w1 < Wc) ? 1.f : 0.f;

    float w00 = (1.f - lh) * (1.f - lw) * vh0 * vw0;
    float w01 = (1.f - lh) * lw         * vh0 * vw1;
    float w10 = lh * (1.f - lw)         * vh1 * vw0;
    float w11 = lh * lw                 * vh1 * vw1;

    int ih0 = min(max(h0, 0), Hc - 1);
    int ih1 = min(max(h1, 0), Hc - 1);
    int iw0 = min(max(w0, 0), Wc - 1);
    int iw1 = min(max(w1, 0), Wc - 1);

    int i00 = ih0 * Wc + iw0;
    int i01 = ih0 * Wc + iw1;
    int i10 = ih1 * Wc + iw0;
    int i11 = ih1 * Wc + iw1;

    const float* xb = x + (size_t)b * Cc * Pc;
    float* colp = g_cols + (size_t)b * CKc * Pc + (size_t)k * Pc + p;

#pragma unroll 8
    for (int c = 0; c < Cc; ++c) {
        const float* xc = xb + (size_t)c * Pc;
        float v = w00 * xc[i00] + w01 * xc[i01] + w10 * xc[i10] + w11 * xc[i11];
        colp[(size_t)c * (Kc * Pc)] = __uint_as_float(cvt_tf32(v));
    }
}

// ---------------------------------------------------------------------------
// Stage 2: tf32 mma.sync GEMM (R9 shape). BM=128, BN=128, BK=32, 3 stages,
// 256 threads, 2 CTAs/SM. issue_tile moved AFTER the mma burst.
// ---------------------------------------------------------------------------
#define BM 128
#define BN 128
#define BK 32
#define NT (CKc / BK)      // 72
#define STAGES 3
#define ASTRB 144
#define ABYTES (BM * ASTRB)          // 18432
#define BSTR 136
#define BBYTES (BK * BSTR * 4)       // 17408
#define SM_TOTAL (STAGES * (ABYTES + BBYTES))   // 107520

__device__ __forceinline__ uint32_t smem_u32(const void* p) {
    uint32_t a;
    asm("{ .reg .u64 t; cvta.to.shared.u64 t, %1; cvt.u32.u64 %0, t; }"
        : "=r"(a) : "l"(p));
    return a;
}
__device__ __forceinline__ void cp_async16(uint32_t dst, const void* src) {
    asm volatile("cp.async.cg.shared.global [%0], [%1], 16;"
                 :: "r"(dst), "l"(src) : "memory");
}
__device__ __forceinline__ void cp_commit() {
    asm volatile("cp.async.commit_group;" ::: "memory");
}
template <int N>
__device__ __forceinline__ void cp_wait() {
    asm volatile("cp.async.wait_group %0;" :: "n"(N) : "memory");
}
__device__ __forceinline__ void ldmx4(uint32_t addr, uint32_t r[4]) {
    asm volatile("ldmatrix.sync.aligned.m8n8.x4.shared.b16 {%0,%1,%2,%3}, [%4];"
                 : "=r"(r[0]), "=r"(r[1]), "=r"(r[2]), "=r"(r[3]) : "r"(addr));
}
__device__ __forceinline__ void mma_tf32(float c[4],
                                         uint32_t a0, uint32_t a1, uint32_t a2, uint32_t a3,
                                         uint32_t b0, uint32_t b1) {
    asm volatile(
        "mma.sync.aligned.m16n8k8.row.col.f32.tf32.tf32.f32 "
        "{%0,%1,%2,%3}, {%4,%5,%6,%7}, {%8,%9}, {%0,%1,%2,%3};"
        : "+f"(c[0]), "+f"(c[1]), "+f"(c[2]), "+f"(c[3])
        : "r"(a0), "r"(a1), "r"(a2), "r"(a3), "r"(b0), "r"(b1));
}

__global__ __launch_bounds__(256, 2) void dcn_gemm_mma(
    float* __restrict__ out)            // [B, OC, P]
{
    extern __shared__ float sm[];
    const uint32_t sbA = smem_u32(sm);
    const uint32_t sbB = sbA + STAGES * ABYTES;
    float* Bs = sm + (STAGES * ABYTES) / 4;

    const int tid = threadIdx.x;
    const int wid = tid >> 5;
    const int lane = tid & 31;
    const int warp_m = wid >> 2;
    const int warp_n = wid & 3;
    const int r = lane >> 2;
    const int c4 = lane & 3;

    const int bx = blockIdx.x;
    const int by = blockIdx.y;
    const int b  = blockIdx.z;

    const float* Ag = g_wtf + (size_t)by * BM * CKc;
    const float* Bg = g_cols + (size_t)b * CKc * Pc + (size_t)bx * BN;

    float acc[4][4][4];
#pragma unroll
    for (int i = 0; i < 4; ++i)
#pragma unroll
        for (int j = 0; j < 4; ++j)
#pragma unroll
            for (int q = 0; q < 4; ++q) acc[i][j][q] = 0.f;

    auto issue_tile = [&](int t) {
        const int buf = t % STAGES;
        const uint32_t abase = sbA + buf * ABYTES;
        const uint32_t bbase = sbB + buf * BBYTES;
#pragma unroll
        for (int i = 0; i < 4; ++i) {
            int ch = tid + i * 256;
            int m = ch >> 3, k4 = ch & 7;
            cp_async16(abase + (uint32_t)(m * ASTRB + k4 * 16),
                       Ag + (size_t)m * CKc + t * BK + k4 * 4);
        }
#pragma unroll
        for (int j = 0; j < 4; ++j) {
            int ch = tid + j * 256;
            int k = ch >> 5, n16 = ch & 31;
            cp_async16(bbase + (uint32_t)(k * (BSTR * 4) + n16 * 16),
                       Bg + (size_t)(t * BK + k) * Pc + n16 * 4);
        }
    };

#pragma unroll
    for (int s = 0; s < STAGES - 1; ++s) { issue_tile(s); cp_commit(); }

    const uint32_t a_lane = (uint32_t)((warp_m * 64 + (lane & 15)) * ASTRB
                                       + ((lane & 16) ? 16 : 0));

    for (int t = 0; t < NT; ++t) {
        const int buf = t % STAGES;
        cp_wait<STAGES - 2>();
        __syncthreads();

        const uint32_t abase = sbA + buf * ABYTES + a_lane;
        const float* Bp = Bs + buf * (BBYTES / 4) + warp_n * 32;

        uint32_t bcur[4][2], bnxt[4][2];
#pragma unroll
        for (int ni = 0; ni < 4; ++ni) {
            int n = ni * 8 + r;
            bcur[ni][0] = __float_as_uint(Bp[(c4    ) * BSTR + n]);
            bcur[ni][1] = __float_as_uint(Bp[(c4 + 4) * BSTR + n]);
        }

#pragma unroll
        for (int kc = 0; kc < 4; ++kc) {
            uint32_t af[4][4];
#pragma unroll
            for (int mi = 0; mi < 4; ++mi)
                ldmx4(abase + (uint32_t)(mi * 16 * ASTRB + kc * 32), af[mi]);

            if (kc < 3) {
                const int kk = (kc + 1) * 8;
#pragma unroll
                for (int ni = 0; ni < 4; ++ni) {
                    int n = ni * 8 + r;
                    bnxt[ni][0] = __float_as_uint(Bp[(kk + c4    ) * BSTR + n]);
                    bnxt[ni][1] = __float_as_uint(Bp[(kk + c4 + 4) * BSTR + n]);
                }
            }

#pragma unroll
            for (int mi = 0; mi < 4; ++mi)
#pragma unroll
                for (int ni = 0; ni < 4; ++ni)
                    mma_tf32(acc[mi][ni], af[mi][0], af[mi][1], af[mi][2], af[mi][3],
                             bcur[ni][0], bcur[ni][1]);

#pragma unroll
            for (int ni = 0; ni < 4; ++ni) {
                bcur[ni][0] = bnxt[ni][0];
                bcur[ni][1] = bnxt[ni][1];
            }
        }

        // issue next-next tile AFTER compute: buf(t+2) == buf(t-1), whose
        // readers all passed this tile's barrier already -> safe.
        if (t + STAGES - 1 < NT) issue_tile(t + STAGES - 1);
        cp_commit();   // always commit -> wait_group counting stays exact
    }

    float* outb = out + ((size_t)b * OCc + by * BM) * Pc + (size_t)bx * BN;
#pragma unroll
    for (int mi = 0; mi < 4; ++mi) {
        int oc0 = warp_m * 64 + mi * 16 + r;
#pragma unroll
        for (int ni = 0; ni < 4; ++ni) {
            int p = warp_n * 32 + ni * 8 + 2 * c4;
            float2 v0 = make_float2(acc[mi][ni][0], acc[mi][ni][1]);
            float2 v1 = make_float2(acc[mi][ni][2], acc[mi][ni][3]);
            *(float2*)(outb + (size_t) oc0      * Pc + p) = v0;
            *(float2*)(outb + (size_t)(oc0 + 8) * Pc + p) = v1;
        }
    }
}

// ---------------------------------------------------------------------------
extern "C" void kernel_launch(void* const* d_in, const int* in_sizes, int n_in,
                              void* d_out, int out_size) {
    const float* x      = (const float*)d_in[0];
    const float* offset = (const float*)d_in[1];
    const float* weight = (const float*)d_in[2];
    float* out = (float*)d_out;

    cudaFuncSetAttribute(dcn_gemm_mma,
                         cudaFuncAttributeMaxDynamicSharedMemorySize, SM_TOTAL);

    dcn_stage01<<<IM2COL_BLOCKS + RW_BLOCKS, 256>>>(x, offset, weight);

    dim3 grid(Pc / BN, OCc / BM, Bc);   // (32, 2, 4) = 256 CTAs, 2 per SM
    dcn_gemm_mma<<<grid, 256, SM_TOTAL>>>(out);
}

// round 16
// speedup vs baseline: 2.5858x; 1.0008x over previous
#include <cuda_runtime.h>
#include <cstdint>

// Problem constants
#define Bc   4
#define Cc   256
#define Hc   64
#define Wc   64
#define OCc  256
#define Kc   9
#define Pc   4096
#define CKc  (Cc*Kc)    // 2304

__device__ float g_cols[(size_t)Bc * CKc * Pc];
__device__ float g_wtf[(size_t)OCc * CKc];      // tf32-rounded weights

__device__ __forceinline__ uint32_t cvt_tf32(float f) {
    uint32_t r;
    asm("cvt.rna.tf32.f32 %0, %1;" : "=r"(r) : "f"(f));
    return r;
}
__device__ __forceinline__ void stcs(float* p, float v) {
    asm volatile("st.global.cs.f32 [%0], %1;" :: "l"(p), "f"(v) : "memory");
}

// ---------------------------------------------------------------------------
// Stage 0+1 merged: blocks [0,576) deformable im2col (streaming stores);
// blocks [576,2880) round weights to tf32.
// ---------------------------------------------------------------------------
#define IM2COL_BLOCKS 576
#define RW_BLOCKS     ((OCc * CKc) / 256)   // 2304

__global__ __launch_bounds__(256) void dcn_stage01(
    const float* __restrict__ x,
    const float* __restrict__ offset,
    const float* __restrict__ w)
{
    if (blockIdx.x >= IM2COL_BLOCKS) {
        int i = (blockIdx.x - IM2COL_BLOCKS) * 256 + threadIdx.x;
        g_wtf[i] = __uint_as_float(cvt_tf32(w[i]));
        return;
    }

    int tid = blockIdx.x * 256 + threadIdx.x;
    int p = tid & (Pc - 1);
    int k = (tid >> 12) % Kc;
    int b = tid / (Pc * Kc);

    int ho = p >> 6;
    int wo = p & 63;
    int ki = k / 3;
    int kj = k - 3 * ki;

    const float* offb = offset + ((size_t)b * 18) * Pc;
    float dy = offb[(2 * k    ) * Pc + p];
    float dx = offb[(2 * k + 1) * Pc + p];

    float ph = (float)(ho - 1 + ki) + dy;
    float pw = (float)(wo - 1 + kj) + dx;

    float h0f = floorf(ph), w0f = floorf(pw);
    float lh = ph - h0f,    lw = pw - w0f;
    int h0 = (int)h0f, w0 = (int)w0f;
    int h1 = h0 + 1,   w1 = w0 + 1;

    float vh0 = (h0 >= 0 && h0 < Hc) ? 1.f : 0.f;
    float vh1 = (h1 >= 0 && h1 < Hc) ? 1.f : 0.f;
    float vw0 = (w0 >= 0 && w0 < Wc) ? 1.f : 0.f;
    float vw1 = (w1 >= 0 && w1 < Wc) ? 1.f : 0.f;

    float w00 = (1.f - lh) * (1.f - lw) * vh0 * vw0;
    float w01 = (1.f - lh) * lw         * vh0 * vw1;
    float w10 = lh * (1.f - lw)         * vh1 * vw0;
    float w11 = lh * lw                 * vh1 * vw1;

    int ih0 = min(max(h0, 0), Hc - 1);
    int ih1 = min(max(h1, 0), Hc - 1);
    int iw0 = min(max(w0, 0), Wc - 1);
    int iw1 = min(max(w1, 0), Wc - 1);

    int i00 = ih0 * Wc + iw0;
    int i01 = ih0 * Wc + iw1;
    int i10 = ih1 * Wc + iw0;
    int i11 = ih1 * Wc + iw1;

    const float* xb = x + (size_t)b * Cc * Pc;
    float* colp = g_cols + (size_t)b * CKc * Pc + (size_t)k * Pc + p;

#pragma unroll 8
    for (int c = 0; c < Cc; ++c) {
        const float* xc = xb + (size_t)c * Pc;
        float v = w00 * xc[i00] + w01 * xc[i01] + w10 * xc[i10] + w11 * xc[i11];
        stcs(colp + (size_t)c * (Kc * Pc), __uint_as_float(cvt_tf32(v)));
    }
}

// ---------------------------------------------------------------------------
// Stage 2: tf32 mma.sync GEMM (R15 shape + per-warp kc rotation).
// BM=128, BN=128, BK=32, 3 stages, 256 threads, 2 CTAs/SM.
// ---------------------------------------------------------------------------
#define BM 128
#define BN 128
#define BK 32
#define NT (CKc / BK)      // 72
#define STAGES 3
#define ASTRB 144
#define ABYTES (BM * ASTRB)          // 18432
#define BSTR 136
#define BBYTES (BK * BSTR * 4)       // 17408
#define SM_TOTAL (STAGES * (ABYTES + BBYTES))   // 107520

__device__ __forceinline__ uint32_t smem_u32(const void* p) {
    uint32_t a;
    asm("{ .reg .u64 t; cvta.to.shared.u64 t, %1; cvt.u32.u64 %0, t; }"
        : "=r"(a) : "l"(p));
    return a;
}
__device__ __forceinline__ void cp_async16(uint32_t dst, const void* src) {
    asm volatile("cp.async.cg.shared.global [%0], [%1], 16;"
                 :: "r"(dst), "l"(src) : "memory");
}
__device__ __forceinline__ void cp_commit() {
    asm volatile("cp.async.commit_group;" ::: "memory");
}
template <int N>
__device__ __forceinline__ void cp_wait() {
    asm volatile("cp.async.wait_group %0;" :: "n"(N) : "memory");
}
__device__ __forceinline__ void ldmx4(uint32_t addr, uint32_t r[4]) {
    asm volatile("ldmatrix.sync.aligned.m8n8.x4.shared.b16 {%0,%1,%2,%3}, [%4];"
                 : "=r"(r[0]), "=r"(r[1]), "=r"(r[2]), "=r"(r[3]) : "r"(addr));
}
__device__ __forceinline__ void mma_tf32(float c[4],
                                         uint32_t a0, uint32_t a1, uint32_t a2, uint32_t a3,
                                         uint32_t b0, uint32_t b1) {
    asm volatile(
        "mma.sync.aligned.m16n8k8.row.col.f32.tf32.tf32.f32 "
        "{%0,%1,%2,%3}, {%4,%5,%6,%7}, {%8,%9}, {%0,%1,%2,%3};"
        : "+f"(c[0]), "+f"(c[1]), "+f"(c[2]), "+f"(c[3])
        : "r"(a0), "r"(a1), "r"(a2), "r"(a3), "r"(b0), "r"(b1));
}

__global__ __launch_bounds__(256, 2) void dcn_gemm_mma(
    float* __restrict__ out)            // [B, OC, P]
{
    extern __shared__ float sm[];
    const uint32_t sbA = smem_u32(sm);
    const uint32_t sbB = sbA + STAGES * ABYTES;
    float* Bs = sm + (STAGES * ABYTES) / 4;

    const int tid = threadIdx.x;
    const int wid = tid >> 5;
    const int lane = tid & 31;
    const int warp_m = wid >> 2;
    const int warp_n = wid & 3;
    const int r = lane >> 2;
    const int c4 = lane & 3;

    const int bx = blockIdx.x;
    const int by = blockIdx.y;
    const int b  = blockIdx.z;

    const float* Ag = g_wtf + (size_t)by * BM * CKc;
    const float* Bg = g_cols + (size_t)b * CKc * Pc + (size_t)bx * BN;

    float acc[4][4][4];
#pragma unroll
    for (int i = 0; i < 4; ++i)
#pragma unroll
        for (int j = 0; j < 4; ++j)
#pragma unroll
            for (int q = 0; q < 4; ++q) acc[i][j][q] = 0.f;

    auto issue_tile = [&](int t) {
        const int buf = t % STAGES;
        const uint32_t abase = sbA + buf * ABYTES;
        const uint32_t bbase = sbB + buf * BBYTES;
#pragma unroll
        for (int i = 0; i < 4; ++i) {
            int ch = tid + i * 256;
            int m = ch >> 3, k4 = ch & 7;
            cp_async16(abase + (uint32_t)(m * ASTRB + k4 * 16),
                       Ag + (size_t)m * CKc + t * BK + k4 * 4);
        }
#pragma unroll
        for (int j = 0; j < 4; ++j) {
            int ch = tid + j * 256;
            int k = ch >> 5, n16 = ch & 31;
            cp_async16(bbase + (uint32_t)(k * (BSTR * 4) + n16 * 16),
                       Bg + (size_t)(t * BK + k) * Pc + n16 * 4);
        }
    };

#pragma unroll
    for (int s = 0; s < STAGES - 1; ++s) { issue_tile(s); cp_commit(); }

    const uint32_t a_lane = (uint32_t)((warp_m * 64 + (lane & 15)) * ASTRB
                                       + ((lane & 16) ? 16 : 0));

    for (int t = 0; t < NT; ++t) {
        const int buf = t % STAGES;
        cp_wait<STAGES - 2>();
        __syncthreads();

        const uint32_t abase = sbA + buf * ABYTES + a_lane;
        const float* Bp = Bs + buf * (BBYTES / 4) + warp_n * 32;

        // per-warp rotated kc order: de-phase crossbar vs mma bursts
        const int kc0 = warp_n;    // 0..3

        uint32_t bcur[4][2], bnxt[4][2];
        {
            const int kk = (kc0 & 3) * 8;
#pragma unroll
            for (int ni = 0; ni < 4; ++ni) {
                int n = ni * 8 + r;
                bcur[ni][0] = __float_as_uint(Bp[(kk + c4    ) * BSTR + n]);
                bcur[ni][1] = __float_as_uint(Bp[(kk + c4 + 4) * BSTR + n]);
            }
        }

#pragma unroll
        for (int kcc = 0; kcc < 4; ++kcc) {
            const int kc = (kcc + kc0) & 3;
            uint32_t af[4][4];
#pragma unroll
            for (int mi = 0; mi < 4; ++mi)
                ldmx4(abase + (uint32_t)(mi * 16 * ASTRB + kc * 32), af[mi]);

            if (kcc < 3) {
                const int kk = (((kcc + 1 + kc0) & 3)) * 8;
#pragma unroll
                for (int ni = 0; ni < 4; ++ni) {
                    int n = ni * 8 + r;
                    bnxt[ni][0] = __float_as_uint(Bp[(kk + c4    ) * BSTR + n]);
                    bnxt[ni][1] = __float_as_uint(Bp[(kk + c4 + 4) * BSTR + n]);
                }
            }

#pragma unroll
            for (int mi = 0; mi < 4; ++mi)
#pragma unroll
                for (int ni = 0; ni < 4; ++ni)
                    mma_tf32(acc[mi][ni], af[mi][0], af[mi][1], af[mi][2], af[mi][3],
                             bcur[ni][0], bcur[ni][1]);

#pragma unroll
            for (int ni = 0; ni < 4; ++ni) {
                bcur[ni][0] = bnxt[ni][0];
                bcur[ni][1] = bnxt[ni][1];
            }
        }

        // issue next-next tile AFTER compute: buf(t+2) == buf(t-1) -> safe
        if (t + STAGES - 1 < NT) issue_tile(t + STAGES - 1);
        cp_commit();
    }

    float* outb = out + ((size_t)b * OCc + by * BM) * Pc + (size_t)bx * BN;
#pragma unroll
    for (int mi = 0; mi < 4; ++mi) {
        int oc0 = warp_m * 64 + mi * 16 + r;
#pragma unroll
        for (int ni = 0; ni < 4; ++ni) {
            int p = warp_n * 32 + ni * 8 + 2 * c4;
            float2 v0 = make_float2(acc[mi][ni][0], acc[mi][ni][1]);
            float2 v1 = make_float2(acc[mi][ni][2], acc[mi][ni][3]);
            *(float2*)(outb + (size_t) oc0      * Pc + p) = v0;
            *(float2*)(outb + (size_t)(oc0 + 8) * Pc + p) = v1;
        }
    }
}

// ---------------------------------------------------------------------------
extern "C" void kernel_launch(void* const* d_in, const int* in_sizes, int n_in,
                              void* d_out, int out_size) {
    const float* x      = (const float*)d_in[0];
    const float* offset = (const float*)d_in[1];
    const float* weight = (const float*)d_in[2];
    float* out = (float*)d_out;

    cudaFuncSetAttribute(dcn_gemm_mma,
                         cudaFuncAttributeMaxDynamicSharedMemorySize, SM_TOTAL);

    dcn_stage01<<<IM2COL_BLOCKS + RW_BLOCKS, 256>>>(x, offset, weight);

    dim3 grid(Pc / BN, OCc / BM, Bc);   // (32, 2, 4) = 256 CTAs, 2 per SM
    dcn_gemm_mma<<<grid, 256, SM_TOTAL>>>(out);
}

// round 17
// speedup vs baseline: 2.8066x; 1.0854x over previous
#include <cuda_runtime.h>
#include <cstdint>

// Problem constants
#define Bc   4
#define Cc   256
#define Hc   64
#define Wc   64
#define OCc  256
#define Kc   9
#define Pc   4096
#define CKc  (Cc*Kc)    // 2304

__device__ float g_cols[(size_t)Bc * CKc * Pc];
__device__ float g_wtf[(size_t)OCc * CKc];      // tf32-rounded weights

__device__ __forceinline__ uint32_t cvt_tf32(float f) {
    uint32_t r;
    asm("cvt.rna.tf32.f32 %0, %1;" : "=r"(r) : "f"(f));
    return r;
}
__device__ __forceinline__ void stcs(float* p, float v) {
    asm volatile("st.global.cs.f32 [%0], %1;" :: "l"(p), "f"(v) : "memory");
}

// ---------------------------------------------------------------------------
// Stage 0+1 merged.
// im2col blocks [0,256): tap-batched — thread = (b, c-quarter, p); computes
// all 9 taps' bilinear metadata once, then loops 64 channels x 9 taps.
// Blocks [256, 256+2304): round weights to tf32.
// ---------------------------------------------------------------------------
#define IM2COL_BLOCKS 256              // B * 4 * P / 256 / ... = 65536/256
#define RW_BLOCKS     ((OCc * CKc) / 256)   // 2304

__global__ __launch_bounds__(256) void dcn_stage01(
    const float* __restrict__ x,
    const float* __restrict__ offset,
    const float* __restrict__ w)
{
    if (blockIdx.x >= IM2COL_BLOCKS) {
        int i = (blockIdx.x - IM2COL_BLOCKS) * 256 + threadIdx.x;
        g_wtf[i] = __uint_as_float(cvt_tf32(w[i]));
        return;
    }

    int q  = blockIdx.x * 256 + threadIdx.x;   // < 65536
    int p  = q & 4095;                         // lanes consecutive in p
    int cq = (q >> 12) & 3;                    // channel quarter
    int b  = q >> 14;

    int ho = p >> 6;
    int wo = p & 63;

    const float* offb = offset + ((size_t)b * 18) * Pc;

    float wt[Kc][4];
    int   ix[Kc][4];
#pragma unroll
    for (int k = 0; k < Kc; ++k) {
        int ki = k / 3;
        int kj = k - 3 * ki;
        float dy = __ldg(offb + (2 * k    ) * Pc + p);
        float dx = __ldg(offb + (2 * k + 1) * Pc + p);

        float ph = (float)(ho - 1 + ki) + dy;
        float pw = (float)(wo - 1 + kj) + dx;
        float h0f = floorf(ph), w0f = floorf(pw);
        float lh = ph - h0f,    lw = pw - w0f;
        int h0 = (int)h0f, w0 = (int)w0f;
        int h1 = h0 + 1,   w1 = w0 + 1;

        float vh0 = (h0 >= 0 && h0 < Hc) ? 1.f : 0.f;
        float vh1 = (h1 >= 0 && h1 < Hc) ? 1.f : 0.f;
        float vw0 = (w0 >= 0 && w0 < Wc) ? 1.f : 0.f;
        float vw1 = (w1 >= 0 && w1 < Wc) ? 1.f : 0.f;

        wt[k][0] = (1.f - lh) * (1.f - lw) * vh0 * vw0;
        wt[k][1] = (1.f - lh) * lw         * vh0 * vw1;
        wt[k][2] = lh * (1.f - lw)         * vh1 * vw0;
        wt[k][3] = lh * lw                 * vh1 * vw1;

        int ih0 = min(max(h0, 0), Hc - 1);
        int ih1 = min(max(h1, 0), Hc - 1);
        int iw0 = min(max(w0, 0), Wc - 1);
        int iw1 = min(max(w1, 0), Wc - 1);
        ix[k][0] = ih0 * Wc + iw0;
        ix[k][1] = ih0 * Wc + iw1;
        ix[k][2] = ih1 * Wc + iw0;
        ix[k][3] = ih1 * Wc + iw1;
    }

    const int c0 = cq * 64;
    const float* xb = x + ((size_t)b * Cc + c0) * Pc;
    float* colb = g_cols + (size_t)b * CKc * Pc + ((size_t)c0 * Kc) * Pc + p;

#pragma unroll 2
    for (int cc = 0; cc < 64; ++cc) {
        const float* xc = xb + (size_t)cc * Pc;
        float* colp = colb + (size_t)cc * (Kc * Pc);
#pragma unroll
        for (int k = 0; k < Kc; ++k) {
            float v = __ldg(xc + ix[k][0]) * wt[k][0]
                    + __ldg(xc + ix[k][1]) * wt[k][1]
                    + __ldg(xc + ix[k][2]) * wt[k][2]
                    + __ldg(xc + ix[k][3]) * wt[k][3];
            stcs(colp + (size_t)k * Pc, __uint_as_float(cvt_tf32(v)));
        }
    }
}

// ---------------------------------------------------------------------------
// Stage 2: tf32 mma.sync GEMM (R16 verbatim — proven 112.4us).
// BM=128, BN=128, BK=32, 3 stages, 256 threads, 2 CTAs/SM.
// ---------------------------------------------------------------------------
#define BM 128
#define BN 128
#define BK 32
#define NT (CKc / BK)      // 72
#define STAGES 3
#define ASTRB 144
#define ABYTES (BM * ASTRB)          // 18432
#define BSTR 136
#define BBYTES (BK * BSTR * 4)       // 17408
#define SM_TOTAL (STAGES * (ABYTES + BBYTES))   // 107520

__device__ __forceinline__ uint32_t smem_u32(const void* p) {
    uint32_t a;
    asm("{ .reg .u64 t; cvta.to.shared.u64 t, %1; cvt.u32.u64 %0, t; }"
        : "=r"(a) : "l"(p));
    return a;
}
__device__ __forceinline__ void cp_async16(uint32_t dst, const void* src) {
    asm volatile("cp.async.cg.shared.global [%0], [%1], 16;"
                 :: "r"(dst), "l"(src) : "memory");
}
__device__ __forceinline__ void cp_commit() {
    asm volatile("cp.async.commit_group;" ::: "memory");
}
template <int N>
__device__ __forceinline__ void cp_wait() {
    asm volatile("cp.async.wait_group %0;" :: "n"(N) : "memory");
}
__device__ __forceinline__ void ldmx4(uint32_t addr, uint32_t r[4]) {
    asm volatile("ldmatrix.sync.aligned.m8n8.x4.shared.b16 {%0,%1,%2,%3}, [%4];"
                 : "=r"(r[0]), "=r"(r[1]), "=r"(r[2]), "=r"(r[3]) : "r"(addr));
}
__device__ __forceinline__ void mma_tf32(float c[4],
                                         uint32_t a0, uint32_t a1, uint32_t a2, uint32_t a3,
                                         uint32_t b0, uint32_t b1) {
    asm volatile(
        "mma.sync.aligned.m16n8k8.row.col.f32.tf32.tf32.f32 "
        "{%0,%1,%2,%3}, {%4,%5,%6,%7}, {%8,%9}, {%0,%1,%2,%3};"
        : "+f"(c[0]), "+f"(c[1]), "+f"(c[2]), "+f"(c[3])
        : "r"(a0), "r"(a1), "r"(a2), "r"(a3), "r"(b0), "r"(b1));
}

__global__ __launch_bounds__(256, 2) void dcn_gemm_mma(
    float* __restrict__ out)            // [B, OC, P]
{
    extern __shared__ float sm[];
    const uint32_t sbA = smem_u32(sm);
    const uint32_t sbB = sbA + STAGES * ABYTES;
    float* Bs = sm + (STAGES * ABYTES) / 4;

    const int tid = threadIdx.x;
    const int wid = tid >> 5;
    const int lane = tid & 31;
    const int warp_m = wid >> 2;
    const int warp_n = wid & 3;
    const int r = lane >> 2;
    const int c4 = lane & 3;

    const int bx = blockIdx.x;
    const int by = blockIdx.y;
    const int b  = blockIdx.z;

    const float* Ag = g_wtf + (size_t)by * BM * CKc;
    const float* Bg = g_cols + (size_t)b * CKc * Pc + (size_t)bx * BN;

    float acc[4][4][4];
#pragma unroll
    for (int i = 0; i < 4; ++i)
#pragma unroll
        for (int j = 0; j < 4; ++j)
#pragma unroll
            for (int q = 0; q < 4; ++q) acc[i][j][q] = 0.f;

    auto issue_tile = [&](int t) {
        const int buf = t % STAGES;
        const uint32_t abase = sbA + buf * ABYTES;
        const uint32_t bbase = sbB + buf * BBYTES;
#pragma unroll
        for (int i = 0; i < 4; ++i) {
            int ch = tid + i * 256;
            int m = ch >> 3, k4 = ch & 7;
            cp_async16(abase + (uint32_t)(m * ASTRB + k4 * 16),
                       Ag + (size_t)m * CKc + t * BK + k4 * 4);
        }
#pragma unroll
        for (int j = 0; j < 4; ++j) {
            int ch = tid + j * 256;
            int k = ch >> 5, n16 = ch & 31;
            cp_async16(bbase + (uint32_t)(k * (BSTR * 4) + n16 * 16),
                       Bg + (size_t)(t * BK + k) * Pc + n16 * 4);
        }
    };

#pragma unroll
    for (int s = 0; s < STAGES - 1; ++s) { issue_tile(s); cp_commit(); }

    const uint32_t a_lane = (uint32_t)((warp_m * 64 + (lane & 15)) * ASTRB
                                       + ((lane & 16) ? 16 : 0));

    for (int t = 0; t < NT; ++t) {
        const int buf = t % STAGES;
        cp_wait<STAGES - 2>();
        __syncthreads();

        const uint32_t abase = sbA + buf * ABYTES + a_lane;
        const float* Bp = Bs + buf * (BBYTES / 4) + warp_n * 32;

        const int kc0 = warp_n;

        uint32_t bcur[4][2], bnxt[4][2];
        {
            const int kk = (kc0 & 3) * 8;
#pragma unroll
            for (int ni = 0; ni < 4; ++ni) {
                int n = ni * 8 + r;
                bcur[ni][0] = __float_as_uint(Bp[(kk + c4    ) * BSTR + n]);
                bcur[ni][1] = __float_as_uint(Bp[(kk + c4 + 4) * BSTR + n]);
            }
        }

#pragma unroll
        for (int kcc = 0; kcc < 4; ++kcc) {
            const int kc = (kcc + kc0) & 3;
            uint32_t af[4][4];
#pragma unroll
            for (int mi = 0; mi < 4; ++mi)
                ldmx4(abase + (uint32_t)(mi * 16 * ASTRB + kc * 32), af[mi]);

            if (kcc < 3) {
                const int kk = (((kcc + 1 + kc0) & 3)) * 8;
#pragma unroll
                for (int ni = 0; ni < 4; ++ni) {
                    int n = ni * 8 + r;
                    bnxt[ni][0] = __float_as_uint(Bp[(kk + c4    ) * BSTR + n]);
                    bnxt[ni][1] = __float_as_uint(Bp[(kk + c4 + 4) * BSTR + n]);
                }
            }

#pragma unroll
            for (int mi = 0; mi < 4; ++mi)
#pragma unroll
                for (int ni = 0; ni < 4; ++ni)
                    mma_tf32(acc[mi][ni], af[mi][0], af[mi][1], af[mi][2], af[mi][3],
                             bcur[ni][0], bcur[ni][1]);

#pragma unroll
            for (int ni = 0; ni < 4; ++ni) {
                bcur[ni][0] = bnxt[ni][0];
                bcur[ni][1] = bnxt[ni][1];
            }
        }

        if (t + STAGES - 1 < NT) issue_tile(t + STAGES - 1);
        cp_commit();
    }

    float* outb = out + ((size_t)b * OCc + by * BM) * Pc + (size_t)bx * BN;
#pragma unroll
    for (int mi = 0; mi < 4; ++mi) {
        int oc0 = warp_m * 64 + mi * 16 + r;
#pragma unroll
        for (int ni = 0; ni < 4; ++ni) {
            int p = warp_n * 32 + ni * 8 + 2 * c4;
            float2 v0 = make_float2(acc[mi][ni][0], acc[mi][ni][1]);
            float2 v1 = make_float2(acc[mi][ni][2], acc[mi][ni][3]);
            *(float2*)(outb + (size_t) oc0      * Pc + p) = v0;
            *(float2*)(outb + (size_t)(oc0 + 8) * Pc + p) = v1;
        }
    }
}

// ---------------------------------------------------------------------------
extern "C" void kernel_launch(void* const* d_in, const int* in_sizes, int n_in,
                              void* d_out, int out_size) {
    const float* x      = (const float*)d_in[0];
    const float* offset = (const float*)d_in[1];
    const float* weight = (const float*)d_in[2];
    float* out = (float*)d_out;

    cudaFuncSetAttribute(dcn_gemm_mma,
                         cudaFuncAttributeMaxDynamicSharedMemorySize, SM_TOTAL);

    dcn_stage01<<<IM2COL_BLOCKS + RW_BLOCKS, 256>>>(x, offset, weight);

    dim3 grid(Pc / BN, OCc / BM, Bc);   // (32, 2, 4) = 256 CTAs, 2 per SM
    dcn_gemm_mma<<<grid, 256, SM_TOTAL>>>(out);
}